// round 5
// baseline (speedup 1.0000x reference)
#include <cuda_runtime.h>
#include <cstdint>

namespace {
constexpr int L2C  = 65536;
constexpr int NC   = 2 * L2C;       // 131072
constexpr int FINC = 8;
constexpr int FOUTC= 8;
constexpr int KC   = 13;
constexpr int IK   = FINC * KC;     // 104
constexpr int EPB  = 32;            // edges per block
constexpr int TPB  = 256;
constexpr int CHE  = 4;             // edges per chunk
constexpr int NCH  = EPB / CHE;     // 8
constexpr int WPEDGE = IK * FOUTC;  // 832 mask words per edge
constexpr int CHW  = CHE * WPEDGE;  // 3328 words per chunk
constexpr int STIT = CHW / TPB;     // 13 (exact)
constexpr int MB32 = CHW / 32 + 2;  // 104 packed words + pad for r1 overread
}

// x transposed to (N, FIN): one gathered column = one 32B sector.
__device__ __align__(16) float g_xt[(size_t)NC * FINC];
// 1 => masks are 1-byte elements; 0 => 4-byte words ({0,1} int or {0,1.0f} float)
__device__ int g_mask_is_byte;

__global__ __launch_bounds__(TPB) void prep_kernel(const float* __restrict__ x,
                                                   const uint32_t* __restrict__ M) {
    if (blockIdx.x == 0 && threadIdx.x < 32) {
        int bad = 0;
        for (int i = threadIdx.x; i < 128; i += 32) {
            uint32_t w = M[i];
            if (!(w == 0u || w == 1u || w == 0x3f800000u)) bad = 1;
        }
        bad = __any_sync(0xffffffffu, bad);
        if (threadIdx.x == 0) g_mask_is_byte = bad;
    }
    int j = blockIdx.x * blockDim.x + threadIdx.x;
    if (j >= NC) return;
    float4 a, b;
    a.x = x[0 * NC + j]; a.y = x[1 * NC + j]; a.z = x[2 * NC + j]; a.w = x[3 * NC + j];
    b.x = x[4 * NC + j]; b.y = x[5 * NC + j]; b.z = x[6 * NC + j]; b.w = x[7 * NC + j];
    float4* dst = reinterpret_cast<float4*>(g_xt) + (size_t)j * 2;
    dst[0] = a;
    dst[1] = b;
}

__global__ __launch_bounds__(TPB) void edge_kernel(
    const float* __restrict__ Wh, const float* __restrict__ Wv,
    const float* __restrict__ bh, const float* __restrict__ bv,
    const uint8_t* __restrict__ Mh, const uint8_t* __restrict__ Mv,
    const int* __restrict__ Kh, const int* __restrict__ Kv,
    const int* __restrict__ ELh, const int* __restrict__ ELv,
    float* __restrict__ out)
{
    const bool vert = (blockIdx.y != 0);
    const float*   W    = vert ? Wv  : Wh;
    const float*   bias = vert ? bv  : bh;
    const uint8_t* M    = vert ? Mv  : Mh;
    const int*     KER  = vert ? Kv  : Kh;
    const int*     EL   = vert ? ELv : ELh;

    __shared__ uint32_t mbuf32[2][MB32];   // bit-packed mask predicates, linear word order
    __shared__ int   kers[EPB * KC];
    __shared__ int   els[EPB];
    __shared__ float bsh[FOUTC];

    const int tid  = threadIdx.x;
    const int lane = tid & 31;
    const int wid  = tid >> 5;
    const int e0   = blockIdx.x * EPB;

    // ---- stage small tables (once) ----
    for (int t = tid; t < EPB * KC; t += TPB) kers[t] = KER[e0 * KC + t];
    if (tid < EPB)   els[tid] = EL[e0 + tid];
    if (tid < FOUTC) bsh[tid] = bias[tid];
    __syncthreads();

    // ---- compute-role decomposition: tid = (cel<2> half<1> oh<2> ii<3>) ----
    const int cel  = tid >> 6;          // chunk-local edge 0..3
    const int half = (tid >> 5) & 1;
    const int oh   = lane >> 3;
    const int ii   = lane & 7;          // input feature
    const int o    = half * 4 + oh;     // output feature
    const int lp   = half * 32 + lane;  // = o*8 + ii, 0..63

    // W row for (o, ii): 13 registers (L1/L2 resident; read once per thread)
    float wreg[KC];
    #pragma unroll
    for (int k = 0; k < KC; k++) wreg[k] = W[lp * KC + k];

    const int isbyte = g_mask_is_byte;
    const uint32_t* Mw = reinterpret_cast<const uint32_t*>(M) + (size_t)e0 * WPEDGE;
    const uint8_t*  M8 = M + (size_t)e0 * WPEDGE;

    // ---- prefetch chunk 0 masks: 13 independent coalesced LDGs ----
    uint32_t pw[STIT];
    if (!isbyte) {
        #pragma unroll
        for (int it = 0; it < STIT; it++) pw[it] = __ldcs(Mw + it * TPB + tid);
    } else {
        #pragma unroll
        for (int it = 0; it < STIT; it++) pw[it] = M8[it * TPB + tid];
    }

    const float SCALE = (float)((2.0 + 2.0 * 2.718281828459045235) /
                                (2.718281828459045235 - 1.0));

    for (int c = 0; c < NCH; c++) {
        const int bsel = c & 1;

        // ---- pack chunk c predicates: ballot #it = preds of 32 consecutive words ----
        uint32_t keep = 0;
        #pragma unroll
        for (int it = 0; it < STIT; it++) {
            uint32_t bm = __ballot_sync(0xffffffffu, pw[it] != 0u);
            if (lane == it) keep = bm;
        }
        if (lane < STIT) mbuf32[bsel][lane * 8 + wid] = keep;   // word m = it*8 + wid

        // ---- prefetch chunk c+1 masks ----
        if (c + 1 < NCH) {
            size_t base = (size_t)(c + 1) * CHW;
            if (!isbyte) {
                #pragma unroll
                for (int it = 0; it < STIT; it++) pw[it] = __ldcs(Mw + base + it * TPB + tid);
            } else {
                #pragma unroll
                for (int it = 0; it < STIT; it++) pw[it] = M8[base + it * TPB + tid];
            }
        }

        // ---- gather x for chunk c straight into registers ----
        const int eg = c * CHE + cel;        // block-local edge
        float xv[KC];
        #pragma unroll
        for (int k = 0; k < KC; k++) {
            int j = kers[eg * KC + k];
            xv[k] = g_xt[(size_t)j * FINC + ii];
        }

        __syncthreads();   // chunk c packed bits visible; buffer reuse safe (2-deep)

        // ---- this thread's 13 mask bits: consecutive at w = cel*832 + lp*13 ----
        const int wbit = cel * WPEDGE + lp * KC;
        uint32_t r0 = mbuf32[bsel][wbit >> 5];
        uint32_t r1 = mbuf32[bsel][(wbit >> 5) + 1];
        uint32_t m  = __funnelshift_r(r0, r1, wbit & 31);

        float acc = 0.0f;
        #pragma unroll
        for (int k = 0; k < KC; k++)
            if (m & (1u << k)) acc = fmaf(wreg[k], xv[k], acc);

        // reduce over input features (lane bits 0..2)
        acc += __shfl_xor_sync(0xffffffffu, acc, 1);
        acc += __shfl_xor_sync(0xffffffffu, acc, 2);
        acc += __shfl_xor_sync(0xffffffffu, acc, 4);

        if (ii == 0) {
            float z = acc + bsh[o];
            float s = 1.0f / (1.0f + __expf(-z));
            out[(size_t)o * NC + els[eg]] = (s - 0.5f) * SCALE;
        }
    }
}

extern "C" void kernel_launch(void* const* d_in, const int* in_sizes, int n_in,
                              void* d_out, int out_size) {
    const float*   x   = (const float*)  d_in[0];
    const float*   Wh  = (const float*)  d_in[1];
    const float*   Wv  = (const float*)  d_in[2];
    const float*   bh  = (const float*)  d_in[3];
    const float*   bv  = (const float*)  d_in[4];
    const uint8_t* Mh  = (const uint8_t*)d_in[5];
    const uint8_t* Mv  = (const uint8_t*)d_in[6];
    const int*     Kh  = (const int*)    d_in[7];
    const int*     Kv  = (const int*)    d_in[8];
    const int*     ELh = (const int*)    d_in[9];
    const int*     ELv = (const int*)    d_in[10];
    float* out = (float*)d_out;

    prep_kernel<<<NC / TPB, TPB>>>(x, (const uint32_t*)Mh);

    dim3 grid(L2C / EPB, 2);   // y=0 horizontal branch, y=1 vertical
    edge_kernel<<<grid, TPB>>>(Wh, Wv, bh, bv, Mh, Mv, Kh, Kv, ELh, ELv, out);
}

// round 6
// speedup vs baseline: 1.2117x; 1.2117x over previous
#include <cuda_runtime.h>
#include <cstdint>

namespace {
constexpr int L2C   = 65536;
constexpr int NC    = 2 * L2C;      // 131072
constexpr int FINC  = 8;
constexpr int FOUTC = 8;
constexpr int KC    = 13;
constexpr int IK    = FINC * KC;    // 104
constexpr int EPB   = 32;           // edges per block
constexpr int TPB   = 256;          // 32 edges x 8 out-features
constexpr int WPEDGE= IK * FOUTC;   // 832 mask elements per edge
constexpr int BLKW  = EPB * WPEDGE; // 26624 mask elements per block
constexpr int U4IT  = BLKW / 4 / TPB;  // 26 staging iterations (word masks)
constexpr int U2IT  = BLKW / 8 / TPB;  // 13 staging iterations (byte masks)
constexpr int WROW  = 108;          // padded W row (floats)
}

// x transposed to (N, FIN): one gathered column = one 32B sector.
__device__ __align__(16) float g_xt[(size_t)NC * FINC];
// 0 = int32 {0,1} words, 1 = float32 {0,1.0f} words, 2 = 1-byte elements
__device__ int g_mask_mode;

__global__ __launch_bounds__(TPB) void prep_kernel(const float* __restrict__ x,
                                                   const uint32_t* __restrict__ M) {
    if (blockIdx.x == 0 && threadIdx.x < 32) {
        int saw1 = 0, sawF = 0, sawO = 0;
        for (int i = threadIdx.x; i < 1024; i += 32) {
            uint32_t w = M[i];
            saw1 |= (w == 1u);
            sawF |= (w == 0x3f800000u);
            sawO |= (w != 0u && w != 1u && w != 0x3f800000u);
        }
        saw1 = __any_sync(0xffffffffu, saw1);
        sawF = __any_sync(0xffffffffu, sawF);
        sawO = __any_sync(0xffffffffu, sawO);
        if (threadIdx.x == 0) g_mask_mode = sawO ? 2 : (sawF ? 1 : 0);
    }
    int j = blockIdx.x * blockDim.x + threadIdx.x;
    if (j >= NC) return;
    float4 a, b;
    a.x = x[0 * NC + j]; a.y = x[1 * NC + j]; a.z = x[2 * NC + j]; a.w = x[3 * NC + j];
    b.x = x[4 * NC + j]; b.y = x[5 * NC + j]; b.z = x[6 * NC + j]; b.w = x[7 * NC + j];
    float4* dst = reinterpret_cast<float4*>(g_xt) + (size_t)j * 2;
    dst[0] = a;
    dst[1] = b;
}

__global__ __launch_bounds__(TPB, 4) void edge_kernel(
    const float* __restrict__ Wh, const float* __restrict__ Wv,
    const float* __restrict__ bh, const float* __restrict__ bv,
    const uint8_t* __restrict__ Mh, const uint8_t* __restrict__ Mv,
    const int* __restrict__ Kh, const int* __restrict__ Kv,
    const int* __restrict__ ELh, const int* __restrict__ ELv,
    float* __restrict__ out)
{
    const bool vert = (blockIdx.y != 0);
    const float*   W    = vert ? Wv  : Wh;
    const float*   bias = vert ? bv  : bh;
    const uint8_t* M    = vert ? Mv  : Mh;
    const int*     KER  = vert ? Kv  : Kh;
    const int*     EL   = vert ? ELv : ELh;

    // mask predicate bytes, LINEAR layout: mb8[u] = pred of mask element u (u = e*832 + o*104 + i*13 + k)
    __shared__ __align__(16) uint8_t mb8[BLKW];          // 26624 B
    __shared__ __align__(16) float   Wsf[FOUTC * WROW];  // 3456 B (padded rows)
    __shared__ __align__(16) float   xsf[EPB * IK];      // 13312 B
    __shared__ int   kers[EPB * KC];
    __shared__ int   els[EPB];
    __shared__ float bsh[FOUTC];

    const int tid = threadIdx.x;
    const int e0  = blockIdx.x * EPB;

    // ---- small tables ----
    for (int t = tid; t < EPB * KC; t += TPB) kers[t] = KER[e0 * KC + t];
    if (tid < EPB)   els[tid] = EL[e0 + tid];
    if (tid < FOUTC) bsh[tid] = bias[tid];
    for (int t = tid; t < FOUTC * IK; t += TPB) {
        int o = t / IK, r = t - o * IK;
        Wsf[o * WROW + r] = W[t];
    }
    __syncthreads();

    const int mode = g_mask_mode;

    // ---- stage mask predicates, linear addressing (no div/mod, no ballot) ----
    if (mode != 2) {
        const uint4* Msrc = reinterpret_cast<const uint4*>(M) + (size_t)e0 * (WPEDGE / 4);
        uint32_t* mb32 = reinterpret_cast<uint32_t*>(mb8);
        if (mode == 0) {   // int32 {0,1}: pred byte = byte0 of each word
            #pragma unroll
            for (int it = 0; it < U4IT; it++) {
                uint4 m = __ldcs(&Msrc[it * TPB + tid]);
                uint32_t lo = __byte_perm(m.x, m.y, 0x0040);
                uint32_t hi = __byte_perm(m.z, m.w, 0x4000);
                mb32[it * TPB + tid] = (lo & 0x0000FFFFu) | (hi & 0xFFFF0000u);
            }
        } else {           // float32 {0,1.0f}: pred byte = byte3 of each word
            #pragma unroll
            for (int it = 0; it < U4IT; it++) {
                uint4 m = __ldcs(&Msrc[it * TPB + tid]);
                uint32_t lo = __byte_perm(m.x, m.y, 0x0073);
                uint32_t hi = __byte_perm(m.z, m.w, 0x7300);
                mb32[it * TPB + tid] = (lo & 0x0000FFFFu) | (hi & 0xFFFF0000u);
            }
        }
    } else {               // already 1-byte elements: copy raw
        const uint2* Msrc = reinterpret_cast<const uint2*>(M + (size_t)e0 * WPEDGE);
        uint2* mb2 = reinterpret_cast<uint2*>(mb8);
        #pragma unroll
        for (int it = 0; it < U2IT; it++)
            mb2[it * TPB + tid] = __ldcs(&Msrc[it * TPB + tid]);
    }

    // ---- gather x once per block: thread (el,o) supplies feature i=o for its edge ----
    {
        const int gel = tid >> 3, gi = tid & 7;
        #pragma unroll
        for (int k = 0; k < KC; k++) {
            int j = kers[gel * KC + k];
            xsf[gel * IK + gi * KC + k] = g_xt[(size_t)j * FINC + gi];
        }
    }
    __syncthreads();

    // ---- compute: thread (el, o) does all 104 elements of one (edge, out-feature) ----
    const int el = tid >> 3;
    const int o  = tid & 7;

    const uint2*  mrow = reinterpret_cast<const uint2*>(mb8 + el * WPEDGE + o * IK);
    const float4* wr   = reinterpret_cast<const float4*>(Wsf + o * WROW);
    const float4* xr   = reinterpret_cast<const float4*>(xsf + el * IK);

    float a0 = 0.f, a1 = 0.f, a2 = 0.f, a3 = 0.f;
    #pragma unroll
    for (int q = 0; q < KC; q++) {                // 13 x 8 elements
        uint2  m  = mrow[q];
        float4 w0 = wr[2 * q],     x0 = xr[2 * q];
        float4 w1 = wr[2 * q + 1], x1 = xr[2 * q + 1];
        if (m.x & 0x000000ffu) a0 = fmaf(w0.x, x0.x, a0);
        if (m.x & 0x0000ff00u) a1 = fmaf(w0.y, x0.y, a1);
        if (m.x & 0x00ff0000u) a2 = fmaf(w0.z, x0.z, a2);
        if (m.x & 0xff000000u) a3 = fmaf(w0.w, x0.w, a3);
        if (m.y & 0x000000ffu) a0 = fmaf(w1.x, x1.x, a0);
        if (m.y & 0x0000ff00u) a1 = fmaf(w1.y, x1.y, a1);
        if (m.y & 0x00ff0000u) a2 = fmaf(w1.z, x1.z, a2);
        if (m.y & 0xff000000u) a3 = fmaf(w1.w, x1.w, a3);
    }

    const float SCALE = (float)((2.0 + 2.0 * 2.718281828459045235) /
                                (2.718281828459045235 - 1.0));
    float z = (a0 + a2) + (a1 + a3) + bsh[o];
    float s = 1.0f / (1.0f + __expf(-z));
    out[(size_t)o * NC + els[el]] = (s - 0.5f) * SCALE;
}

extern "C" void kernel_launch(void* const* d_in, const int* in_sizes, int n_in,
                              void* d_out, int out_size) {
    const float*   x   = (const float*)  d_in[0];
    const float*   Wh  = (const float*)  d_in[1];
    const float*   Wv  = (const float*)  d_in[2];
    const float*   bh  = (const float*)  d_in[3];
    const float*   bv  = (const float*)  d_in[4];
    const uint8_t* Mh  = (const uint8_t*)d_in[5];
    const uint8_t* Mv  = (const uint8_t*)d_in[6];
    const int*     Kh  = (const int*)    d_in[7];
    const int*     Kv  = (const int*)    d_in[8];
    const int*     ELh = (const int*)    d_in[9];
    const int*     ELv = (const int*)    d_in[10];
    float* out = (float*)d_out;

    prep_kernel<<<NC / TPB, TPB>>>(x, (const uint32_t*)Mh);

    dim3 grid(L2C / EPB, 2);   // y=0 horizontal branch, y=1 vertical
    edge_kernel<<<grid, TPB>>>(Wh, Wv, bh, bv, Mh, Mv, Kh, Kv, ELh, ELv, out);
}

// round 7
// speedup vs baseline: 1.3681x; 1.1291x over previous
#include <cuda_runtime.h>
#include <cstdint>

namespace {
constexpr int L2C   = 65536;
constexpr int NC    = 2 * L2C;      // 131072
constexpr int FINC  = 8;
constexpr int FOUTC = 8;
constexpr int KC    = 13;
constexpr int IK    = FINC * KC;    // 104
constexpr int EPB   = 32;           // edges per block
constexpr int TPB   = 256;
constexpr int CHE   = 4;            // edges per chunk
constexpr int NCH   = EPB / CHE;    // 8 chunks
constexpr int WPE   = IK * FOUTC;   // 832 mask elements per edge
constexpr int CHWRD = CHE * WPE;    // 3328 elements per chunk
constexpr int CHB_W = CHWRD * 4;    // 13312 B per chunk (word masks)
}

// x transposed to (N, FIN): one gathered column = one 32B sector.
__device__ __align__(16) float g_xt[(size_t)NC * FINC];
// 0 => 4-byte mask words ({0,1} int32 or {0,1.0f} float32); 1 => 1-byte elements
__device__ int g_mask_is_byte;

__global__ __launch_bounds__(TPB) void prep_kernel(const float* __restrict__ x,
                                                   const uint32_t* __restrict__ M) {
    if (blockIdx.x == 0 && threadIdx.x < 32) {
        int bad = 0;
        for (int i = threadIdx.x; i < 1024; i += 32) {
            uint32_t w = M[i];
            if (!(w == 0u || w == 1u || w == 0x3f800000u)) bad = 1;
        }
        bad = __any_sync(0xffffffffu, bad);
        if (threadIdx.x == 0) g_mask_is_byte = bad;
    }
    int j = blockIdx.x * blockDim.x + threadIdx.x;
    if (j >= NC) return;
    float4 a, b;
    a.x = x[0 * NC + j]; a.y = x[1 * NC + j]; a.z = x[2 * NC + j]; a.w = x[3 * NC + j];
    b.x = x[4 * NC + j]; b.y = x[5 * NC + j]; b.z = x[6 * NC + j]; b.w = x[7 * NC + j];
    float4* dst = reinterpret_cast<float4*>(g_xt) + (size_t)j * 2;
    dst[0] = a;
    dst[1] = b;
}

__device__ __forceinline__ void cp16(uint32_t dst_smem, const void* src) {
    asm volatile("cp.async.cg.shared.global [%0], [%1], 16;"
                 :: "r"(dst_smem), "l"(src) : "memory");
}
__device__ __forceinline__ void cp_commit() {
    asm volatile("cp.async.commit_group;" ::: "memory");
}
template <int N> __device__ __forceinline__ void cp_wait() {
    asm volatile("cp.async.wait_group %0;" :: "n"(N) : "memory");
}

__global__ __launch_bounds__(TPB, 5) void edge_kernel(
    const float* __restrict__ Wh, const float* __restrict__ Wv,
    const float* __restrict__ bh, const float* __restrict__ bv,
    const uint8_t* __restrict__ Mh, const uint8_t* __restrict__ Mv,
    const int* __restrict__ Kh, const int* __restrict__ Kv,
    const int* __restrict__ ELh, const int* __restrict__ ELv,
    float* __restrict__ out)
{
    const bool vert = (blockIdx.y != 0);
    const float*   W    = vert ? Wv  : Wh;
    const float*   bias = vert ? bv  : bh;
    const uint8_t* M    = vert ? Mv  : Mh;
    const int*     KER  = vert ? Kv  : Kh;
    const int*     EL   = vert ? ELv : ELh;

    // raw mask chunk ring (2 stages). Word mode uses CHB_W bytes/stage; byte mode CHWRD bytes.
    __shared__ __align__(16) uint32_t mbuf[2 * CHWRD];     // 26624 B
    __shared__ __align__(16) float    xsf[EPB * IK];       // 13312 B
    __shared__ int   kers[EPB * KC];
    __shared__ int   els[EPB];
    __shared__ float bsh[FOUTC];

    const int tid = threadIdx.x;
    const int e0  = blockIdx.x * EPB;

    // ---- small tables ----
    for (int t = tid; t < EPB * KC; t += TPB) kers[t] = KER[e0 * KC + t];
    if (tid < EPB)   els[tid] = EL[e0 + tid];
    if (tid < FOUTC) bsh[tid] = bias[tid];

    // ---- roles: tid = cel<2b> | lp<6b>,  lp = o*8 + i ----
    const int cel  = tid >> 6;           // chunk-local edge 0..3
    const int lp   = tid & 63;
    const int o    = lp >> 3;
    const int ii   = lp & 7;
    const int lane = tid & 31;           // ii = lane & 7

    // W row (o, ii): 13 registers, L2-resident reload per block
    float wreg[KC];
    #pragma unroll
    for (int k = 0; k < KC; k++) wreg[k] = W[lp * KC + k];

    const int isbyte = g_mask_is_byte;
    const int esz    = isbyte ? 1 : 4;
    const int chb    = CHWRD * esz;                 // bytes per chunk
    const int nops   = chb >> 4;                    // 16B cp.async ops per chunk
    const uint8_t* Mbase = M + (size_t)e0 * WPE * esz;
    const uint32_t mb_s  = (uint32_t)__cvta_generic_to_shared(mbuf);

    // ---- stage chunk 0 (async) ----
    for (int u = tid; u < nops; u += TPB)
        cp16(mb_s + u * 16, Mbase + (size_t)u * 16);
    cp_commit();

    __syncthreads();   // kers visible for gather

    // ---- gather x once per block: thread (gel, gi) supplies feature gi of edge gel ----
    {
        const int gel = tid >> 3, gi = tid & 7;
        #pragma unroll
        for (int k = 0; k < KC; k++) {
            int j = kers[gel * KC + k];
            xsf[gel * IK + gi * KC + k] = g_xt[(size_t)j * FINC + gi];
        }
    }

    const float SCALE = (float)((2.0 + 2.0 * 2.718281828459045235) /
                                (2.718281828459045235 - 1.0));

    for (int c = 0; c < NCH; c++) {
        const int bsel = c & 1;

        // ---- issue chunk c+1 into the other buffer ----
        if (c + 1 < NCH) {
            const uint8_t* src = Mbase + (size_t)(c + 1) * chb;
            const uint32_t dst = mb_s + (bsel ^ 1) * CHB_W;
            for (int u = tid; u < nops; u += TPB)
                cp16(dst + u * 16, src + (size_t)u * 16);
            cp_commit();
            cp_wait<1>();      // chunk c complete
        } else {
            cp_wait<0>();
        }
        __syncthreads();       // publish chunk c; xsf ready (c==0)

        // ---- compute chunk c: thread (cel, o, ii) does 13 MACs ----
        const int eg = c * CHE + cel;
        const float* xrow = &xsf[eg * IK + ii * KC];

        float acc = 0.0f;
        if (!isbyte) {
            const uint32_t* mrow = mbuf + bsel * CHWRD + cel * WPE + lp * KC;
            #pragma unroll
            for (int k = 0; k < KC; k++)
                if (mrow[k]) acc = fmaf(wreg[k], xrow[k], acc);
        } else {
            const uint8_t* mrow = reinterpret_cast<const uint8_t*>(mbuf) +
                                  bsel * CHB_W + cel * WPE + lp * KC;
            #pragma unroll
            for (int k = 0; k < KC; k++)
                if (mrow[k]) acc = fmaf(wreg[k], xrow[k], acc);
        }

        // reduce over input features (lane bits 0..2)
        acc += __shfl_xor_sync(0xffffffffu, acc, 1);
        acc += __shfl_xor_sync(0xffffffffu, acc, 2);
        acc += __shfl_xor_sync(0xffffffffu, acc, 4);

        if (ii == 0) {
            float z = acc + bsh[o];
            float s = 1.0f / (1.0f + __expf(-z));
            out[(size_t)o * NC + els[eg]] = (s - 0.5f) * SCALE;
        }
        __syncthreads();       // chunk-c buffer free for reuse at iteration c+1
    }
}

extern "C" void kernel_launch(void* const* d_in, const int* in_sizes, int n_in,
                              void* d_out, int out_size) {
    const float*   x   = (const float*)  d_in[0];
    const float*   Wh  = (const float*)  d_in[1];
    const float*   Wv  = (const float*)  d_in[2];
    const float*   bh  = (const float*)  d_in[3];
    const float*   bv  = (const float*)  d_in[4];
    const uint8_t* Mh  = (const uint8_t*)d_in[5];
    const uint8_t* Mv  = (const uint8_t*)d_in[6];
    const int*     Kh  = (const int*)    d_in[7];
    const int*     Kv  = (const int*)    d_in[8];
    const int*     ELh = (const int*)    d_in[9];
    const int*     ELv = (const int*)    d_in[10];
    float* out = (float*)d_out;

    prep_kernel<<<NC / TPB, TPB>>>(x, (const uint32_t*)Mh);

    dim3 grid(L2C / EPB, 2);   // y=0 horizontal branch, y=1 vertical
    edge_kernel<<<grid, TPB>>>(Wh, Wv, bh, bv, Mh, Mv, Kh, Kv, ELh, ELv, out);
}